// round 6
// baseline (speedup 1.0000x reference)
#include <cuda_runtime.h>
#include <math.h>
#include <float.h>

#define G    1024
#define NSV  16
#define NTRK 64
#define KNN  8

typedef unsigned long long u64;

// ---------------- scratch (static device globals: no allocation) ----------------
__device__ float g_sv [G*NSV *128];
__device__ float g_trk[G*NTRK*128];
__device__ float g_U1 [G*NTRK*128];
__device__ float g_U2 [G*NTRK*128];
__device__ float g_V1 [G*NSV *128];
__device__ float g_V2 [G*NTRK*128];
__device__ float g_f1 [G*NTRK*128];

__device__ __forceinline__ float eluf(float x) { return x > 0.f ? x : expm1f(x); }

// ---- packed f32x2 helpers ----
__device__ __forceinline__ u64 splat2(float a) {
    u64 r; asm("mov.b64 %0, {%1, %1};" : "=l"(r) : "f"(a)); return r;
}
__device__ __forceinline__ void ffma2(u64& c, u64 a, u64 b) {
    asm("fma.rn.f32x2 %0, %1, %2, %0;" : "+l"(c) : "l"(a), "l"(b));
}
__device__ __forceinline__ float2 unpack2(u64 v) {
    float2 f; asm("mov.b64 {%0, %1}, %2;" : "=f"(f.x), "=f"(f.y) : "l"(v)); return f;
}

// ---- 32-k weight chunk staging, 512 threads ----
// MODE 0: W[k][c] (plain, 128x128)
// MODE 1: W[k][c] - W[128+k][c] (diff of 256x128)
// MODE 2: W[128+k][c] (bottom half of 256x128)
template<int MODE>
__device__ __forceinline__ void stage_chunk(float* dst, const float* __restrict__ W,
                                            int kc, int tid)
{
    #pragma unroll
    for (int e = 0; e < 2; e++) {
        int i4 = tid + e * 512;                 // 0..1023 float4s = 32x128 chunk
        float4 w;
        if (MODE == 0) {
            w = ((const float4*)W)[kc * 1024 + i4];
        } else if (MODE == 1) {
            w = ((const float4*)W)[kc * 1024 + i4];
            float4 w2 = ((const float4*)W)[4096 + kc * 1024 + i4];
            w.x -= w2.x; w.y -= w2.y; w.z -= w2.z; w.w -= w2.w;
        } else {
            w = ((const float4*)W)[4096 + kc * 1024 + i4];
        }
        ((float4*)dst)[i4] = w;
    }
}

// ---- GEMM core over one 32-k chunk, 512 threads ----
// Hs: [k][r] ld 132 (rows = M tile of 128); Ws: [k][c] ld 128.
// Thread (tx=tid&15, ty=tid>>4): rows ty*4+ii, col pairs 2tx+32j. Conflict-free.
__device__ __forceinline__ void zero_acc(u64 acc[4][4]) {
    #pragma unroll
    for (int i = 0; i < 4; i++)
        #pragma unroll
        for (int j = 0; j < 4; j++) acc[i][j] = 0ull;
}
__device__ __forceinline__ void gemm_chunk(const float* __restrict__ Hs,
                                           const float* __restrict__ Ws,
                                           u64 acc[4][4], int tx, int ty)
{
    #pragma unroll 8
    for (int kk = 0; kk < 32; kk++) {
        float4 a = *(const float4*)&Hs[kk * 132 + ty * 4];
        const u64* br = (const u64*)&Ws[kk * 128];
        u64 b0 = br[tx], b1 = br[tx + 16], b2 = br[tx + 32], b3 = br[tx + 48];
        u64 s;
        s = splat2(a.x); ffma2(acc[0][0],s,b0); ffma2(acc[0][1],s,b1); ffma2(acc[0][2],s,b2); ffma2(acc[0][3],s,b3);
        s = splat2(a.y); ffma2(acc[1][0],s,b0); ffma2(acc[1][1],s,b1); ffma2(acc[1][2],s,b2); ffma2(acc[1][3],s,b3);
        s = splat2(a.z); ffma2(acc[2][0],s,b0); ffma2(acc[2][1],s,b1); ffma2(acc[2][2],s,b2); ffma2(acc[2][3],s,b3);
        s = splat2(a.w); ffma2(acc[3][0],s,b0); ffma2(acc[3][1],s,b1); ffma2(acc[3][2],s,b2); ffma2(acc[3][3],s,b3);
    }
}
// full 128-k pass with double-buffered weight streaming
template<int MODE>
__device__ __forceinline__ void gemm_pass(const float* __restrict__ Hs, float* Wb,
                                          const float* __restrict__ W,
                                          u64 acc[4][4], int tid, int tx, int ty)
{
    stage_chunk<MODE>(Wb, W, 0, tid);
    __syncthreads();
    #pragma unroll
    for (int kc = 0; kc < 4; kc++) {
        if (kc < 3) stage_chunk<MODE>(Wb + ((kc + 1) & 1) * 4096, W, kc + 1, tid);
        gemm_chunk(Hs + kc * 32 * 132, Wb + (kc & 1) * 4096, acc, tx, ty);
        __syncthreads();
    }
}
__device__ __forceinline__ void store512(const u64 acc[4][4], float* __restrict__ C,
                                         size_t row0, int tx, int ty,
                                         const float* __restrict__ bias)
{
    float2 bv[4] = {{0,0},{0,0},{0,0},{0,0}};
    if (bias) {
        #pragma unroll
        for (int j = 0; j < 4; j++) bv[j] = *(const float2*)&bias[tx * 2 + j * 32];
    }
    #pragma unroll
    for (int ii = 0; ii < 4; ii++) {
        size_t r = row0 + ty * 4 + ii;
        #pragma unroll
        for (int j = 0; j < 4; j++) {
            float2 p = unpack2(acc[ii][j]);
            p.x += bv[j].x; p.y += bv[j].y;
            *(float2*)&C[r * 128 + tx * 2 + j * 32] = p;
        }
    }
}

// =====================================================================
// Node kernels: layer1 -> Hs (transposed); pass1 = relu(Hs@W2+b2) -> Yf
// and back into Hs; then NPASS-1 more weight-streamed GEMM passes.
// 512 threads, 128-row tile, smem ~109KB -> 2 blocks/SM.
// =====================================================================
template<int IN, int NPASS>
__global__ __launch_bounds__(512)
void node_kernel(const float* __restrict__ X,
                 const float* __restrict__ W1, const float* __restrict__ b1,
                 const float* __restrict__ W2, const float* __restrict__ b2,
                 const float* __restrict__ Wc1, const float* __restrict__ bc1,
                 const float* __restrict__ Wc2, const float* __restrict__ bc2,
                 float* __restrict__ Yf, float* __restrict__ Y1, float* __restrict__ Y2)
{
    extern __shared__ float sm[];
    float* Hs  = sm;                    // 128*132 = 16896
    float* Wb  = Hs + 16896;            // 2*4096
    float* Xin = Wb + 8192;             // 128*IN
    float* W1s = Xin + 128 * IN;        // IN*128
    float* b1s = W1s + IN * 128;        // 128
    const int tid = threadIdx.x;
    const int tx = tid & 15, ty = tid >> 4;
    const size_t row0 = (size_t)blockIdx.x * 128;

    for (int t = tid; t < 128 * IN; t += 512) Xin[t] = X[row0 * IN + t];
    for (int t = tid; t < IN * 128; t += 512) W1s[t] = W1[t];
    if (tid < 128) b1s[tid] = b1[tid];
    __syncthreads();

    // layer 1 -> Hs transposed [c][r]
    {
        int r = tid >> 2, ch = (tid & 3) * 32;
        float xr[IN];
        #pragma unroll
        for (int d = 0; d < IN; d++) xr[d] = Xin[r * IN + d];
        #pragma unroll 4
        for (int cc = 0; cc < 32; cc++) {
            int c = ch + cc;
            float a = b1s[c];
            #pragma unroll
            for (int d = 0; d < IN; d++) a = fmaf(xr[d], W1s[d * 128 + c], a);
            Hs[c * 132 + r] = eluf(a);
        }
    }
    // (gemm_pass's initial stage+sync orders Hs writes before reads)

    u64 acc[4][4];
    zero_acc(acc);
    gemm_pass<0>(Hs, Wb, W2, acc, tid, tx, ty);

    // feats = relu(acc + b2) -> Yf and Hs (transposed, in place)
    {
        float2 bv[4];
        #pragma unroll
        for (int j = 0; j < 4; j++) bv[j] = *(const float2*)&b2[tx * 2 + j * 32];
        #pragma unroll
        for (int ii = 0; ii < 4; ii++) {
            int rr = ty * 4 + ii;
            #pragma unroll
            for (int j = 0; j < 4; j++) {
                float2 p = unpack2(acc[ii][j]);
                float va = fmaxf(p.x + bv[j].x, 0.f);
                float vb = fmaxf(p.y + bv[j].y, 0.f);
                int c = tx * 2 + j * 32;
                float2 o = {va, vb};
                *(float2*)&Yf[(row0 + rr) * 128 + c] = o;
                Hs[c * 132 + rr]       = va;
                Hs[(c + 1) * 132 + rr] = vb;
            }
        }
    }

    zero_acc(acc);
    if (NPASS == 3) gemm_pass<1>(Hs, Wb, Wc1, acc, tid, tx, ty);
    else            gemm_pass<2>(Hs, Wb, Wc1, acc, tid, tx, ty);
    store512(acc, Y1, row0, tx, ty, (NPASS == 3) ? bc1 : nullptr);

    if (NPASS == 3) {
        zero_acc(acc);
        gemm_pass<1>(Hs, Wb, Wc2, acc, tid, tx, ty);
        store512(acc, Y2, row0, tx, ty, bc2);
    }
}

// =====================================================================
// V2 = f1 @ Wc2_bot. Both X and W streamed in 32-k double-buffered
// chunks. smem ~65KB -> 3 blocks/SM.
// =====================================================================
__global__ __launch_bounds__(512)
void gemm_v2(const float* __restrict__ X, const float* __restrict__ W,
             float* __restrict__ C)
{
    extern __shared__ float sm[];
    float* Xb = sm;                 // 2 * 32*132
    float* Wb = Xb + 2 * 4224;      // 2 * 32*128
    const int tid = threadIdx.x;
    const int tx = tid & 15, ty = tid >> 4;
    const size_t row0 = (size_t)blockIdx.x * 128;

    auto stage_x = [&](float* dst, int kc) {
        #pragma unroll
        for (int e = 0; e < 2; e++) {
            int t = tid + e * 512;
            int row = t >> 3;
            int kq  = (t & 7) * 4;
            float4 v = *(const float4*)&X[(row0 + row) * 128 + kc * 32 + kq];
            dst[(kq + 0) * 132 + row] = v.x;
            dst[(kq + 1) * 132 + row] = v.y;
            dst[(kq + 2) * 132 + row] = v.z;
            dst[(kq + 3) * 132 + row] = v.w;
        }
    };

    stage_x(Xb, 0);
    stage_chunk<2>(Wb, W, 0, tid);
    __syncthreads();

    u64 acc[4][4];
    zero_acc(acc);
    #pragma unroll
    for (int kc = 0; kc < 4; kc++) {
        if (kc < 3) {
            stage_x(Xb + ((kc + 1) & 1) * 4224, kc + 1);
            stage_chunk<2>(Wb + ((kc + 1) & 1) * 4096, W, kc + 1, tid);
        }
        gemm_chunk(Xb + (kc & 1) * 4224, Wb + (kc & 1) * 4096, acc, tx, ty);
        __syncthreads();
    }
    store512(acc, C, row0, tx, ty, nullptr);
}

// =====================================================================
// conv1: kNN(trk -> 16 SVs) + gather-max + ELU -> f1. 512 threads/graph.
// =====================================================================
__global__ __launch_bounds__(512)
void conv1_kernel(const float* __restrict__ trkF, const float* __restrict__ svF,
                  const float* __restrict__ U,    const float* __restrict__ V,
                  float* __restrict__ f1out)
{
    extern __shared__ float sm[];
    float* dsh = sm;                    // 64*130
    float* ssh = dsh + 64 * 130;        // 16*130
    float* vsh = ssh + 16 * 130;        // 16*130
    float* sc  = vsh + 16 * 130;        // 64*17
    float* sn2 = sc + 64 * 17;          // 16
    int*  idxs = (int*)(sn2 + 16);      // 64*8

    const int g   = blockIdx.x;
    const int tid = threadIdx.x;
    const int wid = tid >> 5, lane = tid & 31;
    const float* dg = trkF + (size_t)g * 64 * 128;
    const float* sg = svF  + (size_t)g * 16 * 128;
    const float* Vg = V    + (size_t)g * 16 * 128;
    const float* Ug = U    + (size_t)g * 64 * 128;

    for (int t = tid; t < 64 * 128; t += 512)
        dsh[(t >> 7) * 130 + (t & 127)] = dg[t];
    for (int t = tid; t < 16 * 128; t += 512) {
        int r = t >> 7, c = t & 127;
        ssh[r * 130 + c] = sg[t];
        vsh[r * 130 + c] = Vg[t];
    }
    __syncthreads();

    if (wid < 16) {
        const float* row = &ssh[wid * 130];
        float e0 = row[lane], e1 = row[32 + lane], e2 = row[64 + lane], e3 = row[96 + lane];
        float s = e0*e0 + e1*e1 + e2*e2 + e3*e3;
        #pragma unroll
        for (int off = 16; off > 0; off >>= 1) s += __shfl_xor_sync(~0u, s, off);
        if (lane == 0) sn2[wid] = s;
    }
    __syncthreads();

    {
        int i = tid >> 3, jj = tid & 7;
        u64 a0 = 0ull, a1 = 0ull;
        #pragma unroll 8
        for (int kk = 0; kk < 64; kk++) {
            u64 av = *(const u64*)&dsh[i * 130 + kk * 2];
            u64 b0 = *(const u64*)&ssh[jj * 130 + kk * 2];
            u64 b1 = *(const u64*)&ssh[(jj + 8) * 130 + kk * 2];
            ffma2(a0, av, b0);
            ffma2(a1, av, b1);
        }
        float2 p = unpack2(a0);
        sc[i * 17 + jj]     = sn2[jj]     - 2.f * (p.x + p.y);
        p = unpack2(a1);
        sc[i * 17 + jj + 8] = sn2[jj + 8] - 2.f * (p.x + p.y);
    }
    __syncthreads();

    #pragma unroll
    for (int q = 0; q < 4; q++) {
        int row = wid * 4 + q;
        float mv = (lane < 16) ? sc[row * 17 + lane] : FLT_MAX;
        #pragma unroll
        for (int n = 0; n < KNN; n++) {
            float cv = mv; int ci = lane;
            #pragma unroll
            for (int off = 16; off > 0; off >>= 1) {
                float ov = __shfl_xor_sync(~0u, cv, off);
                int   oi = __shfl_xor_sync(~0u, ci, off);
                if (ov < cv || (ov == cv && oi < ci)) { cv = ov; ci = oi; }
            }
            if (lane == 0) idxs[row * 8 + n] = ci;
            if (lane == ci) mv = FLT_MAX;
        }
    }
    __syncthreads();

    {
        int c = tid & 127, ih = tid >> 7;
        for (int i0 = 0; i0 < 64; i0 += 4) {
            int i = i0 + ih;
            const int* ip = &idxs[i * 8];
            float vmax = -FLT_MAX;
            #pragma unroll
            for (int n = 0; n < KNN; n++) vmax = fmaxf(vmax, vsh[ip[n] * 130 + c]);
            f1out[((size_t)g * 64 + i) * 128 + c] = eluf(Ug[i * 128 + c] + vmax);
        }
    }
}

// =====================================================================
// conv2 + mean pool + head. 512 threads/graph, smem ~88KB.
// =====================================================================
__global__ __launch_bounds__(512)
void conv2_head_kernel(const float* __restrict__ trkF, const float* __restrict__ f1,
                       const float* __restrict__ U,    const float* __restrict__ V,
                       const float* __restrict__ Wo1, const float* __restrict__ bo1,
                       const float* __restrict__ Wo2, const float* __restrict__ bo2,
                       const float* __restrict__ Wo3, const float* __restrict__ bo3,
                       const float* __restrict__ Wo4, const float* __restrict__ bo4,
                       float* __restrict__ out, int out_size)
{
    extern __shared__ float sm[];
    float* dsh = sm;                    // 64*130
    float* ssh = dsh + 64 * 130;        // 64*130 (f1, later V)
    float* sc  = ssh + 64 * 130;        // 64*65
    float* sn2 = sc + 64 * 65;          // 64
    float* colsum = sn2 + 64;           // 512
    float* pooled = colsum + 512;       // 128
    float* h1 = pooled + 128;           // 64
    float* h2 = h1 + 64;                // 32
    float* h3 = h2 + 32;                // 4
    int*  idxs = (int*)(h3 + 4);        // 64*8

    const int g   = blockIdx.x;
    const int tid = threadIdx.x;
    const int wid = tid >> 5, lane = tid & 31;
    const float* dg = trkF + (size_t)g * 64 * 128;
    const float* sg = f1   + (size_t)g * 64 * 128;
    const float* Vg = V    + (size_t)g * 64 * 128;
    const float* Ug = U    + (size_t)g * 64 * 128;

    for (int t = tid; t < 64 * 128; t += 512) {
        int r = t >> 7, c = t & 127;
        dsh[r * 130 + c] = dg[t];
        ssh[r * 130 + c] = sg[t];
    }
    __syncthreads();

    #pragma unroll
    for (int q = 0; q < 4; q++) {
        int row = wid * 4 + q;
        const float* rp = &ssh[row * 130];
        float e0 = rp[lane], e1 = rp[32 + lane], e2 = rp[64 + lane], e3 = rp[96 + lane];
        float s = e0*e0 + e1*e1 + e2*e2 + e3*e3;
        #pragma unroll
        for (int off = 16; off > 0; off >>= 1) s += __shfl_xor_sync(~0u, s, off);
        if (lane == 0) sn2[row] = s;
    }
    __syncthreads();

    {
        const int tx = tid & 15, ty = tid >> 4;
        u64 acc[2][4];
        #pragma unroll
        for (int a = 0; a < 2; a++)
            #pragma unroll
            for (int b = 0; b < 4; b++) acc[a][b] = 0ull;
        #pragma unroll 8
        for (int kk = 0; kk < 64; kk++) {
            u64 av0 = *(const u64*)&dsh[(ty * 2) * 130 + kk * 2];
            u64 av1 = *(const u64*)&dsh[(ty * 2 + 1) * 130 + kk * 2];
            #pragma unroll
            for (int jj = 0; jj < 4; jj++) {
                u64 bv = *(const u64*)&ssh[(tx + jj * 16) * 130 + kk * 2];
                ffma2(acc[0][jj], av0, bv);
                ffma2(acc[1][jj], av1, bv);
            }
        }
        #pragma unroll
        for (int ii = 0; ii < 2; ii++)
            #pragma unroll
            for (int jj = 0; jj < 4; jj++) {
                float2 p = unpack2(acc[ii][jj]);
                int j = tx + jj * 16;
                sc[(ty * 2 + ii) * 65 + j] = sn2[j] - 2.f * (p.x + p.y);
            }
    }
    __syncthreads();

    #pragma unroll
    for (int q = 0; q < 4; q++) {
        int row = wid * 4 + q;
        float v0 = sc[row * 65 + lane];
        float v1 = sc[row * 65 + 32 + lane];
        #pragma unroll
        for (int n = 0; n < KNN; n++) {
            float cv; int ci;
            if (v1 < v0) { cv = v1; ci = lane + 32; }
            else         { cv = v0; ci = lane; }
            #pragma unroll
            for (int off = 16; off > 0; off >>= 1) {
                float ov = __shfl_xor_sync(~0u, cv, off);
                int   oi = __shfl_xor_sync(~0u, ci, off);
                if (ov < cv || (ov == cv && oi < ci)) { cv = ov; ci = oi; }
            }
            if (lane == 0) idxs[row * 8 + n] = ci;
            if (ci == lane)           v0 = FLT_MAX;
            else if (ci == lane + 32) v1 = FLT_MAX;
        }
    }
    __syncthreads();

    for (int t = tid; t < 64 * 128; t += 512)
        ssh[(t >> 7) * 130 + (t & 127)] = Vg[t];
    __syncthreads();

    {
        int c = tid & 127, ih = tid >> 7;
        float csum = 0.f;
        for (int i0 = 0; i0 < 64; i0 += 4) {
            int i = i0 + ih;
            const int* ip = &idxs[i * 8];
            float vmax = -FLT_MAX;
            #pragma unroll
            for (int n = 0; n < KNN; n++) vmax = fmaxf(vmax, ssh[ip[n] * 130 + c]);
            csum += eluf(Ug[i * 128 + c] + vmax);
        }
        colsum[ih * 128 + c] = csum;
    }
    __syncthreads();
    if (tid < 128)
        pooled[tid] = (colsum[tid] + colsum[128 + tid] + colsum[256 + tid] + colsum[384 + tid]) * (1.f / 64.f);
    __syncthreads();
    if (tid < 64) {
        float a = bo1[tid];
        #pragma unroll 8
        for (int d = 0; d < 128; d++) a += pooled[d] * Wo1[d * 64 + tid];
        h1[tid] = eluf(a);
    }
    __syncthreads();
    if (tid < 32) {
        float a = bo2[tid];
        #pragma unroll 8
        for (int d = 0; d < 64; d++) a += h1[d] * Wo2[d * 32 + tid];
        h2[tid] = eluf(a);
    }
    __syncthreads();
    if (tid < 4) {
        float a = bo3[tid];
        #pragma unroll
        for (int d = 0; d < 32; d++) a += h2[d] * Wo3[d * 4 + tid];
        h3[tid] = eluf(a);
    }
    __syncthreads();
    if (tid == 0) {
        float a = bo4[0];
        #pragma unroll
        for (int d = 0; d < 4; d++) a += h3[d] * Wo4[d];
        out[g] = a;
        if (out_size >= 2 * G) out[G + g] = (float)g;
    }
}

// ---------------- launch ----------------
extern "C" void kernel_launch(void* const* d_in, const int* in_sizes, int n_in,
                              void* d_out, int out_size)
{
    const float* x_sv   = (const float*)d_in[0];
    const float* x_trk  = (const float*)d_in[1];
    const float* W_sv1  = (const float*)d_in[2];
    const float* b_sv1  = (const float*)d_in[3];
    const float* W_sv2  = (const float*)d_in[4];
    const float* b_sv2  = (const float*)d_in[5];
    const float* W_trk1 = (const float*)d_in[6];
    const float* b_trk1 = (const float*)d_in[7];
    const float* W_trk2 = (const float*)d_in[8];
    const float* b_trk2 = (const float*)d_in[9];
    const float* W_c1   = (const float*)d_in[10];
    const float* b_c1   = (const float*)d_in[11];
    const float* W_c2   = (const float*)d_in[12];
    const float* b_c2   = (const float*)d_in[13];
    const float* W_o1   = (const float*)d_in[14];
    const float* b_o1   = (const float*)d_in[15];
    const float* W_o2   = (const float*)d_in[16];
    const float* b_o2   = (const float*)d_in[17];
    const float* W_o3   = (const float*)d_in[18];
    const float* b_o3   = (const float*)d_in[19];
    const float* W_o4   = (const float*)d_in[20];
    const float* b_o4   = (const float*)d_in[21];
    float* out = (float*)d_out;

    float *p_sv, *p_trk, *p_U1, *p_U2, *p_V1, *p_V2, *p_f1;
    cudaGetSymbolAddress((void**)&p_sv,  g_sv);
    cudaGetSymbolAddress((void**)&p_trk, g_trk);
    cudaGetSymbolAddress((void**)&p_U1,  g_U1);
    cudaGetSymbolAddress((void**)&p_U2,  g_U2);
    cudaGetSymbolAddress((void**)&p_V1,  g_V1);
    cudaGetSymbolAddress((void**)&p_V2,  g_V2);
    cudaGetSymbolAddress((void**)&p_f1,  g_f1);

    const int smem_a = (16896 + 8192 + 128*2 + 2*128 + 128) * 4;
    const int smem_b = (16896 + 8192 + 128*8 + 8*128 + 128) * 4;
    const int smem_g = (2*4224 + 2*4096) * 4;
    const int smem_c = (64*130 + 16*130 + 16*130 + 64*17 + 16) * 4 + 64*8*4;
    const int smem_d = (64*130 + 64*130 + 64*65 + 64 + 512 + 128 + 64 + 32 + 4) * 4 + 64*8*4;

    (void)cudaFuncSetAttribute(node_kernel<2,2>,  cudaFuncAttributeMaxDynamicSharedMemorySize, smem_a);
    (void)cudaFuncSetAttribute(node_kernel<8,3>,  cudaFuncAttributeMaxDynamicSharedMemorySize, smem_b);
    (void)cudaFuncSetAttribute(gemm_v2,           cudaFuncAttributeMaxDynamicSharedMemorySize, smem_g);
    (void)cudaFuncSetAttribute(conv1_kernel,      cudaFuncAttributeMaxDynamicSharedMemorySize, smem_c);
    (void)cudaFuncSetAttribute(conv2_head_kernel, cudaFuncAttributeMaxDynamicSharedMemorySize, smem_d);

    // A: sv MLP + V1
    node_kernel<2,2><<<G * NSV / 128, 512, smem_a>>>(
        x_sv, W_sv1, b_sv1, W_sv2, b_sv2, W_c1, nullptr, nullptr, nullptr,
        p_sv, p_V1, nullptr);

    // B: trk MLP + U1 + U2
    node_kernel<8,3><<<G * NTRK / 128, 512, smem_b>>>(
        x_trk, W_trk1, b_trk1, W_trk2, b_trk2, W_c1, b_c1, W_c2, b_c2,
        p_trk, p_U1, p_U2);

    // C: conv1 -> f1
    conv1_kernel<<<G, 512, smem_c>>>(p_trk, p_sv, p_U1, p_V1, p_f1);

    // V2 = f1 @ Wc2_bot
    gemm_v2<<<G * NTRK / 128, 512, smem_g>>>(p_f1, W_c2, p_V2);

    // D: conv2 + head
    conv2_head_kernel<<<G, 512, smem_d>>>(p_trk, p_f1, p_U2, p_V2,
        W_o1, b_o1, W_o2, b_o2, W_o3, b_o3, W_o4, b_o4, out, out_size);
}

// round 7
// speedup vs baseline: 1.1009x; 1.1009x over previous
#include <cuda_runtime.h>
#include <math.h>
#include <float.h>

#define G    1024
#define NSV  16
#define NTRK 64
#define KNN  8

typedef unsigned long long u64;

// ---------------- scratch (static device globals: no allocation) ----------------
__device__ float g_sv [G*NSV *128];
__device__ float g_trk[G*NTRK*128];
__device__ float g_U1 [G*NTRK*128];
__device__ float g_U2 [G*NTRK*128];
__device__ float g_V1 [G*NSV *128];
__device__ float g_V2 [G*NTRK*128];
__device__ float g_f1 [G*NTRK*128];

__device__ __forceinline__ float eluf(float x) { return x > 0.f ? x : expm1f(x); }

// ---- packed f32x2 helpers ----
__device__ __forceinline__ u64 splat2(float a) {
    u64 r; asm("mov.b64 %0, {%1, %1};" : "=l"(r) : "f"(a)); return r;
}
__device__ __forceinline__ void ffma2(u64& c, u64 a, u64 b) {
    asm("fma.rn.f32x2 %0, %1, %2, %0;" : "+l"(c) : "l"(a), "l"(b));
}
__device__ __forceinline__ float2 unpack2(u64 v) {
    float2 f; asm("mov.b64 {%0, %1}, %2;" : "=f"(f.x), "=f"(f.y) : "l"(v)); return f;
}

// ---- 32-k weight chunk staging, 512 threads ----
// MODE 0: W[k][c]; MODE 1: W[k][c]-W[128+k][c]; MODE 2: W[128+k][c]
template<int MODE>
__device__ __forceinline__ void stage_chunk(float* dst, const float* __restrict__ W,
                                            int kc, int tid)
{
    #pragma unroll
    for (int e = 0; e < 2; e++) {
        int i4 = tid + e * 512;
        float4 w;
        if (MODE == 0) {
            w = ((const float4*)W)[kc * 1024 + i4];
        } else if (MODE == 1) {
            w = ((const float4*)W)[kc * 1024 + i4];
            float4 w2 = ((const float4*)W)[4096 + kc * 1024 + i4];
            w.x -= w2.x; w.y -= w2.y; w.z -= w2.z; w.w -= w2.w;
        } else {
            w = ((const float4*)W)[4096 + kc * 1024 + i4];
        }
        ((float4*)dst)[i4] = w;
    }
}
// full 128x128 bottom-half stage (for gemm_v2)
__device__ __forceinline__ void stage_bot_full(float* Ws, const float* __restrict__ W, int tid) {
    #pragma unroll
    for (int e = 0; e < 8; e++)
        ((float4*)Ws)[tid + e * 512] = ((const float4*)W)[tid + e * 512 + 4096];
}

// ---- GEMM core over one 32-k chunk, 512 threads ----
// Hs: [k][r] ld 132; Ws: [k][c] ld 128. Conflict-free.
__device__ __forceinline__ void zero_acc(u64 acc[4][4]) {
    #pragma unroll
    for (int i = 0; i < 4; i++)
        #pragma unroll
        for (int j = 0; j < 4; j++) acc[i][j] = 0ull;
}
__device__ __forceinline__ void gemm_chunk(const float* __restrict__ Hs,
                                           const float* __restrict__ Ws,
                                           u64 acc[4][4], int tx, int ty)
{
    #pragma unroll 8
    for (int kk = 0; kk < 32; kk++) {
        float4 a = *(const float4*)&Hs[kk * 132 + ty * 4];
        const u64* br = (const u64*)&Ws[kk * 128];
        u64 b0 = br[tx], b1 = br[tx + 16], b2 = br[tx + 32], b3 = br[tx + 48];
        u64 s;
        s = splat2(a.x); ffma2(acc[0][0],s,b0); ffma2(acc[0][1],s,b1); ffma2(acc[0][2],s,b2); ffma2(acc[0][3],s,b3);
        s = splat2(a.y); ffma2(acc[1][0],s,b0); ffma2(acc[1][1],s,b1); ffma2(acc[1][2],s,b2); ffma2(acc[1][3],s,b3);
        s = splat2(a.z); ffma2(acc[2][0],s,b0); ffma2(acc[2][1],s,b1); ffma2(acc[2][2],s,b2); ffma2(acc[2][3],s,b3);
        s = splat2(a.w); ffma2(acc[3][0],s,b0); ffma2(acc[3][1],s,b1); ffma2(acc[3][2],s,b2); ffma2(acc[3][3],s,b3);
    }
}
// full 128-k pass with double-buffered weight streaming
template<int MODE>
__device__ __forceinline__ void gemm_pass(const float* __restrict__ Hs, float* Wb,
                                          const float* __restrict__ W,
                                          u64 acc[4][4], int tid, int tx, int ty)
{
    stage_chunk<MODE>(Wb, W, 0, tid);
    __syncthreads();
    #pragma unroll
    for (int kc = 0; kc < 4; kc++) {
        if (kc < 3) stage_chunk<MODE>(Wb + ((kc + 1) & 1) * 4096, W, kc + 1, tid);
        gemm_chunk(Hs + kc * 32 * 132, Wb + (kc & 1) * 4096, acc, tx, ty);
        __syncthreads();
    }
}
__device__ __forceinline__ void store512(const u64 acc[4][4], float* __restrict__ C,
                                         size_t row0, int tx, int ty,
                                         const float* __restrict__ bias)
{
    float2 bv[4] = {{0,0},{0,0},{0,0},{0,0}};
    if (bias) {
        #pragma unroll
        for (int j = 0; j < 4; j++) bv[j] = *(const float2*)&bias[tx * 2 + j * 32];
    }
    #pragma unroll
    for (int ii = 0; ii < 4; ii++) {
        size_t r = row0 + ty * 4 + ii;
        #pragma unroll
        for (int j = 0; j < 4; j++) {
            float2 p = unpack2(acc[ii][j]);
            p.x += bv[j].x; p.y += bv[j].y;
            *(float2*)&C[r * 128 + tx * 2 + j * 32] = p;
        }
    }
}

// =====================================================================
// Node kernels: layer1 -> Hs; pass1 = relu(Hs@W2+b2) -> Yf + Hs;
// then NPASS-1 more weight-streamed GEMM passes.
// 512 threads, 128-row tile, smem ~107KB, regs capped for 2 blocks/SM.
// =====================================================================
template<int IN, int NPASS>
__global__ __launch_bounds__(512, 2)
void node_kernel(const float* __restrict__ X,
                 const float* __restrict__ W1, const float* __restrict__ b1,
                 const float* __restrict__ W2, const float* __restrict__ b2,
                 const float* __restrict__ Wc1, const float* __restrict__ bc1,
                 const float* __restrict__ Wc2, const float* __restrict__ bc2,
                 float* __restrict__ Yf, float* __restrict__ Y1, float* __restrict__ Y2)
{
    extern __shared__ float sm[];
    float* Hs  = sm;                    // 128*132 = 16896
    float* Wb  = Hs + 16896;            // 2*4096
    float* Xin = Wb + 8192;             // 128*IN
    float* W1s = Xin + 128 * IN;        // IN*128
    float* b1s = W1s + IN * 128;        // 128
    const int tid = threadIdx.x;
    const int tx = tid & 15, ty = tid >> 4;
    const size_t row0 = (size_t)blockIdx.x * 128;

    for (int t = tid; t < 128 * IN; t += 512) Xin[t] = X[row0 * IN + t];
    for (int t = tid; t < IN * 128; t += 512) W1s[t] = W1[t];
    if (tid < 128) b1s[tid] = b1[tid];
    __syncthreads();

    // layer 1 -> Hs transposed [c][r]
    {
        int r = tid >> 2, ch = (tid & 3) * 32;
        float xr[IN];
        #pragma unroll
        for (int d = 0; d < IN; d++) xr[d] = Xin[r * IN + d];
        #pragma unroll 4
        for (int cc = 0; cc < 32; cc++) {
            int c = ch + cc;
            float a = b1s[c];
            #pragma unroll
            for (int d = 0; d < IN; d++) a = fmaf(xr[d], W1s[d * 128 + c], a);
            Hs[c * 132 + r] = eluf(a);
        }
    }
    // (gemm_pass's initial stage+sync orders Hs writes before reads)

    u64 acc[4][4];
    zero_acc(acc);
    gemm_pass<0>(Hs, Wb, W2, acc, tid, tx, ty);

    // feats = relu(acc + b2) -> Yf and Hs (transposed, in place)
    {
        float2 bv[4];
        #pragma unroll
        for (int j = 0; j < 4; j++) bv[j] = *(const float2*)&b2[tx * 2 + j * 32];
        #pragma unroll
        for (int ii = 0; ii < 4; ii++) {
            int rr = ty * 4 + ii;
            #pragma unroll
            for (int j = 0; j < 4; j++) {
                float2 p = unpack2(acc[ii][j]);
                float va = fmaxf(p.x + bv[j].x, 0.f);
                float vb = fmaxf(p.y + bv[j].y, 0.f);
                int c = tx * 2 + j * 32;
                float2 o = {va, vb};
                *(float2*)&Yf[(row0 + rr) * 128 + c] = o;
                Hs[c * 132 + rr]       = va;
                Hs[(c + 1) * 132 + rr] = vb;
            }
        }
    }

    zero_acc(acc);
    if (NPASS == 3) gemm_pass<1>(Hs, Wb, Wc1, acc, tid, tx, ty);
    else            gemm_pass<2>(Hs, Wb, Wc1, acc, tid, tx, ty);
    store512(acc, Y1, row0, tx, ty, (NPASS == 3) ? bc1 : nullptr);

    if (NPASS == 3) {
        zero_acc(acc);
        gemm_pass<1>(Hs, Wb, Wc2, acc, tid, tx, ty);
        store512(acc, Y2, row0, tx, ty, bc2);
    }
}

// =====================================================================
// V2 = f1 @ Wc2_bot. R5 variant: monolithic W tile + single-buffer
// chunked X staging. 62 regs -> 2 blocks/SM.
// =====================================================================
__global__ __launch_bounds__(512, 2)
void gemm_v2(const float* __restrict__ X, const float* __restrict__ W,
             float* __restrict__ C)
{
    extern __shared__ float sm[];
    float* Ws = sm;              // 16384
    float* Xs = sm + 16384;      // 32*132 transposed [k][row]
    const int tid = threadIdx.x;
    const int tx = tid & 15, ty = tid >> 4;
    const size_t row0 = (size_t)blockIdx.x * 128;

    stage_bot_full(Ws, W, tid);

    u64 acc[4][4];
    zero_acc(acc);

    for (int kc = 0; kc < 4; kc++) {
        __syncthreads();
        #pragma unroll
        for (int e = 0; e < 2; e++) {
            int t = tid + e * 512;
            int row = t >> 3;
            int kq  = (t & 7) * 4;
            float4 v = *(const float4*)&X[(row0 + row) * 128 + kc * 32 + kq];
            Xs[(kq + 0) * 132 + row] = v.x;
            Xs[(kq + 1) * 132 + row] = v.y;
            Xs[(kq + 2) * 132 + row] = v.z;
            Xs[(kq + 3) * 132 + row] = v.w;
        }
        __syncthreads();
        gemm_chunk(Xs, Ws + kc * 32 * 128, acc, tx, ty);
    }
    store512(acc, C, row0, tx, ty, nullptr);
}

// =====================================================================
// conv1: kNN(trk -> 16 SVs) + gather-max + ELU -> f1. 512 threads/graph.
// =====================================================================
__global__ __launch_bounds__(512)
void conv1_kernel(const float* __restrict__ trkF, const float* __restrict__ svF,
                  const float* __restrict__ U,    const float* __restrict__ V,
                  float* __restrict__ f1out)
{
    extern __shared__ float sm[];
    float* dsh = sm;                    // 64*130
    float* ssh = dsh + 64 * 130;        // 16*130
    float* vsh = ssh + 16 * 130;        // 16*130
    float* sc  = vsh + 16 * 130;        // 64*17
    float* sn2 = sc + 64 * 17;          // 16
    int*  idxs = (int*)(sn2 + 16);      // 64*8

    const int g   = blockIdx.x;
    const int tid = threadIdx.x;
    const int wid = tid >> 5, lane = tid & 31;
    const float* dg = trkF + (size_t)g * 64 * 128;
    const float* sg = svF  + (size_t)g * 16 * 128;
    const float* Vg = V    + (size_t)g * 16 * 128;
    const float* Ug = U    + (size_t)g * 64 * 128;

    for (int t = tid; t < 64 * 128; t += 512)
        dsh[(t >> 7) * 130 + (t & 127)] = dg[t];
    for (int t = tid; t < 16 * 128; t += 512) {
        int r = t >> 7, c = t & 127;
        ssh[r * 130 + c] = sg[t];
        vsh[r * 130 + c] = Vg[t];
    }
    __syncthreads();

    if (wid < 16) {
        const float* row = &ssh[wid * 130];
        float e0 = row[lane], e1 = row[32 + lane], e2 = row[64 + lane], e3 = row[96 + lane];
        float s = e0*e0 + e1*e1 + e2*e2 + e3*e3;
        #pragma unroll
        for (int off = 16; off > 0; off >>= 1) s += __shfl_xor_sync(~0u, s, off);
        if (lane == 0) sn2[wid] = s;
    }
    __syncthreads();

    {
        int i = tid >> 3, jj = tid & 7;
        u64 a0 = 0ull, a1 = 0ull;
        #pragma unroll 8
        for (int kk = 0; kk < 64; kk++) {
            u64 av = *(const u64*)&dsh[i * 130 + kk * 2];
            u64 b0 = *(const u64*)&ssh[jj * 130 + kk * 2];
            u64 b1 = *(const u64*)&ssh[(jj + 8) * 130 + kk * 2];
            ffma2(a0, av, b0);
            ffma2(a1, av, b1);
        }
        float2 p = unpack2(a0);
        sc[i * 17 + jj]     = sn2[jj]     - 2.f * (p.x + p.y);
        p = unpack2(a1);
        sc[i * 17 + jj + 8] = sn2[jj + 8] - 2.f * (p.x + p.y);
    }
    __syncthreads();

    #pragma unroll
    for (int q = 0; q < 4; q++) {
        int row = wid * 4 + q;
        float mv = (lane < 16) ? sc[row * 17 + lane] : FLT_MAX;
        #pragma unroll
        for (int n = 0; n < KNN; n++) {
            float cv = mv; int ci = lane;
            #pragma unroll
            for (int off = 16; off > 0; off >>= 1) {
                float ov = __shfl_xor_sync(~0u, cv, off);
                int   oi = __shfl_xor_sync(~0u, ci, off);
                if (ov < cv || (ov == cv && oi < ci)) { cv = ov; ci = oi; }
            }
            if (lane == 0) idxs[row * 8 + n] = ci;
            if (lane == ci) mv = FLT_MAX;
        }
    }
    __syncthreads();

    {
        int c = tid & 127, ih = tid >> 7;
        for (int i0 = 0; i0 < 64; i0 += 4) {
            int i = i0 + ih;
            const int* ip = &idxs[i * 8];
            float vmax = -FLT_MAX;
            #pragma unroll
            for (int n = 0; n < KNN; n++) vmax = fmaxf(vmax, vsh[ip[n] * 130 + c]);
            f1out[((size_t)g * 64 + i) * 128 + c] = eluf(Ug[i * 128 + c] + vmax);
        }
    }
}

// =====================================================================
// conv2 + mean pool + head. 512 threads/graph. V loaded into the dead
// dst buffer BEFORE top-k so the LDGs overlap the shuffle phase.
// =====================================================================
__global__ __launch_bounds__(512)
void conv2_head_kernel(const float* __restrict__ trkF, const float* __restrict__ f1,
                       const float* __restrict__ U,    const float* __restrict__ V,
                       const float* __restrict__ Wo1, const float* __restrict__ bo1,
                       const float* __restrict__ Wo2, const float* __restrict__ bo2,
                       const float* __restrict__ Wo3, const float* __restrict__ bo3,
                       const float* __restrict__ Wo4, const float* __restrict__ bo4,
                       float* __restrict__ out, int out_size)
{
    extern __shared__ float sm[];
    float* dsh = sm;                    // 64*130 (trk, later V)
    float* ssh = dsh + 64 * 130;        // 64*130 (f1)
    float* sc  = ssh + 64 * 130;        // 64*65
    float* sn2 = sc + 64 * 65;          // 64
    float* colsum = sn2 + 64;           // 512
    float* pooled = colsum + 512;       // 128
    float* h1 = pooled + 128;           // 64
    float* h2 = h1 + 64;                // 32
    float* h3 = h2 + 32;                // 4
    int*  idxs = (int*)(h3 + 4);        // 64*8

    const int g   = blockIdx.x;
    const int tid = threadIdx.x;
    const int wid = tid >> 5, lane = tid & 31;
    const float* dg = trkF + (size_t)g * 64 * 128;
    const float* sg = f1   + (size_t)g * 64 * 128;
    const float* Vg = V    + (size_t)g * 64 * 128;
    const float* Ug = U    + (size_t)g * 64 * 128;

    for (int t = tid; t < 64 * 128; t += 512) {
        int r = t >> 7, c = t & 127;
        dsh[r * 130 + c] = dg[t];
        ssh[r * 130 + c] = sg[t];
    }
    __syncthreads();

    #pragma unroll
    for (int q = 0; q < 4; q++) {
        int row = wid * 4 + q;
        const float* rp = &ssh[row * 130];
        float e0 = rp[lane], e1 = rp[32 + lane], e2 = rp[64 + lane], e3 = rp[96 + lane];
        float s = e0*e0 + e1*e1 + e2*e2 + e3*e3;
        #pragma unroll
        for (int off = 16; off > 0; off >>= 1) s += __shfl_xor_sync(~0u, s, off);
        if (lane == 0) sn2[row] = s;
    }
    __syncthreads();

    {
        const int tx = tid & 15, ty = tid >> 4;
        u64 acc[2][4];
        #pragma unroll
        for (int a = 0; a < 2; a++)
            #pragma unroll
            for (int b = 0; b < 4; b++) acc[a][b] = 0ull;
        #pragma unroll 8
        for (int kk = 0; kk < 64; kk++) {
            u64 av0 = *(const u64*)&dsh[(ty * 2) * 130 + kk * 2];
            u64 av1 = *(const u64*)&dsh[(ty * 2 + 1) * 130 + kk * 2];
            #pragma unroll
            for (int jj = 0; jj < 4; jj++) {
                u64 bv = *(const u64*)&ssh[(tx + jj * 16) * 130 + kk * 2];
                ffma2(acc[0][jj], av0, bv);
                ffma2(acc[1][jj], av1, bv);
            }
        }
        #pragma unroll
        for (int ii = 0; ii < 2; ii++)
            #pragma unroll
            for (int jj = 0; jj < 4; jj++) {
                float2 p = unpack2(acc[ii][jj]);
                int j = tx + jj * 16;
                sc[(ty * 2 + ii) * 65 + j] = sn2[j] - 2.f * (p.x + p.y);
            }
    }
    __syncthreads();

    // overwrite dsh with V tile (LDGs overlap the top-k shuffles below)
    for (int t = tid; t < 64 * 128; t += 512)
        dsh[(t >> 7) * 130 + (t & 127)] = Vg[t];

    // warp-parallel top-8 over 64 candidates (2 per lane)
    #pragma unroll
    for (int q = 0; q < 4; q++) {
        int row = wid * 4 + q;
        float v0 = sc[row * 65 + lane];
        float v1 = sc[row * 65 + 32 + lane];
        #pragma unroll
        for (int n = 0; n < KNN; n++) {
            float cv; int ci;
            if (v1 < v0) { cv = v1; ci = lane + 32; }
            else         { cv = v0; ci = lane; }
            #pragma unroll
            for (int off = 16; off > 0; off >>= 1) {
                float ov = __shfl_xor_sync(~0u, cv, off);
                int   oi = __shfl_xor_sync(~0u, ci, off);
                if (ov < cv || (ov == cv && oi < ci)) { cv = ov; ci = oi; }
            }
            if (lane == 0) idxs[row * 8 + n] = ci;
            if (ci == lane)           v0 = FLT_MAX;
            else if (ci == lane + 32) v1 = FLT_MAX;
        }
    }
    __syncthreads();

    {
        int c = tid & 127, ih = tid >> 7;
        float csum = 0.f;
        for (int i0 = 0; i0 < 64; i0 += 4) {
            int i = i0 + ih;
            const int* ip = &idxs[i * 8];
            float vmax = -FLT_MAX;
            #pragma unroll
            for (int n = 0; n < KNN; n++) vmax = fmaxf(vmax, dsh[ip[n] * 130 + c]);
            csum += eluf(Ug[i * 128 + c] + vmax);
        }
        colsum[ih * 128 + c] = csum;
    }
    __syncthreads();
    if (tid < 128)
        pooled[tid] = (colsum[tid] + colsum[128 + tid] + colsum[256 + tid] + colsum[384 + tid]) * (1.f / 64.f);
    __syncthreads();
    if (tid < 64) {
        float a = bo1[tid];
        #pragma unroll 8
        for (int d = 0; d < 128; d++) a += pooled[d] * Wo1[d * 64 + tid];
        h1[tid] = eluf(a);
    }
    __syncthreads();
    if (tid < 32) {
        float a = bo2[tid];
        #pragma unroll 8
        for (int d = 0; d < 64; d++) a += h1[d] * Wo2[d * 32 + tid];
        h2[tid] = eluf(a);
    }
    __syncthreads();
    if (tid < 4) {
        float a = bo3[tid];
        #pragma unroll
        for (int d = 0; d < 32; d++) a += h2[d] * Wo3[d * 4 + tid];
        h3[tid] = eluf(a);
    }
    __syncthreads();
    if (tid == 0) {
        float a = bo4[0];
        #pragma unroll
        for (int d = 0; d < 4; d++) a += h3[d] * Wo4[d];
        out[g] = a;
        if (out_size >= 2 * G) out[G + g] = (float)g;
    }
}

// ---------------- launch ----------------
extern "C" void kernel_launch(void* const* d_in, const int* in_sizes, int n_in,
                              void* d_out, int out_size)
{
    const float* x_sv   = (const float*)d_in[0];
    const float* x_trk  = (const float*)d_in[1];
    const float* W_sv1  = (const float*)d_in[2];
    const float* b_sv1  = (const float*)d_in[3];
    const float* W_sv2  = (const float*)d_in[4];
    const float* b_sv2  = (const float*)d_in[5];
    const float* W_trk1 = (const float*)d_in[6];
    const float* b_trk1 = (const float*)d_in[7];
    const float* W_trk2 = (const float*)d_in[8];
    const float* b_trk2 = (const float*)d_in[9];
    const float* W_c1   = (const float*)d_in[10];
    const float* b_c1   = (const float*)d_in[11];
    const float* W_c2   = (const float*)d_in[12];
    const float* b_c2   = (const float*)d_in[13];
    const float* W_o1   = (const float*)d_in[14];
    const float* b_o1   = (const float*)d_in[15];
    const float* W_o2   = (const float*)d_in[16];
    const float* b_o2   = (const float*)d_in[17];
    const float* W_o3   = (const float*)d_in[18];
    const float* b_o3   = (const float*)d_in[19];
    const float* W_o4   = (const float*)d_in[20];
    const float* b_o4   = (const float*)d_in[21];
    float* out = (float*)d_out;

    float *p_sv, *p_trk, *p_U1, *p_U2, *p_V1, *p_V2, *p_f1;
    cudaGetSymbolAddress((void**)&p_sv,  g_sv);
    cudaGetSymbolAddress((void**)&p_trk, g_trk);
    cudaGetSymbolAddress((void**)&p_U1,  g_U1);
    cudaGetSymbolAddress((void**)&p_U2,  g_U2);
    cudaGetSymbolAddress((void**)&p_V1,  g_V1);
    cudaGetSymbolAddress((void**)&p_V2,  g_V2);
    cudaGetSymbolAddress((void**)&p_f1,  g_f1);

    const int smem_a = (16896 + 8192 + 128*2 + 2*128 + 128) * 4;
    const int smem_b = (16896 + 8192 + 128*8 + 8*128 + 128) * 4;
    const int smem_g = (16384 + 32*132) * 4;
    const int smem_c = (64*130 + 16*130 + 16*130 + 64*17 + 16) * 4 + 64*8*4;
    const int smem_d = (64*130 + 64*130 + 64*65 + 64 + 512 + 128 + 64 + 32 + 4) * 4 + 64*8*4;

    (void)cudaFuncSetAttribute(node_kernel<2,2>,  cudaFuncAttributeMaxDynamicSharedMemorySize, smem_a);
    (void)cudaFuncSetAttribute(node_kernel<8,3>,  cudaFuncAttributeMaxDynamicSharedMemorySize, smem_b);
    (void)cudaFuncSetAttribute(gemm_v2,           cudaFuncAttributeMaxDynamicSharedMemorySize, smem_g);
    (void)cudaFuncSetAttribute(conv1_kernel,      cudaFuncAttributeMaxDynamicSharedMemorySize, smem_c);
    (void)cudaFuncSetAttribute(conv2_head_kernel, cudaFuncAttributeMaxDynamicSharedMemorySize, smem_d);

    // A: sv MLP + V1
    node_kernel<2,2><<<G * NSV / 128, 512, smem_a>>>(
        x_sv, W_sv1, b_sv1, W_sv2, b_sv2, W_c1, nullptr, nullptr, nullptr,
        p_sv, p_V1, nullptr);

    // B: trk MLP + U1 + U2
    node_kernel<8,3><<<G * NTRK / 128, 512, smem_b>>>(
        x_trk, W_trk1, b_trk1, W_trk2, b_trk2, W_c1, b_c1, W_c2, b_c2,
        p_trk, p_U1, p_U2);

    // C: conv1 -> f1
    conv1_kernel<<<G, 512, smem_c>>>(p_trk, p_sv, p_U1, p_V1, p_f1);

    // V2 = f1 @ Wc2_bot
    gemm_v2<<<G * NTRK / 128, 512, smem_g>>>(p_f1, W_c2, p_V2);

    // D: conv2 + head
    conv2_head_kernel<<<G, 512, smem_d>>>(p_trk, p_f1, p_U2, p_V2,
        W_o1, b_o1, W_o2, b_o2, W_o3, b_o3, W_o4, b_o4, out, out_size);
}

// round 8
// speedup vs baseline: 1.1406x; 1.0361x over previous
#include <cuda_runtime.h>
#include <math.h>
#include <float.h>

#define G    1024
#define NSV  16
#define NTRK 64
#define KNN  8

typedef unsigned long long u64;

// ---------------- scratch (static device globals: no allocation) ----------------
__device__ float g_sv [G*NSV *128];
__device__ float g_trk[G*NTRK*128];
__device__ float g_U1 [G*NTRK*128];
__device__ float g_U2 [G*NTRK*128];
__device__ float g_V1 [G*NSV *128];
__device__ float g_V2 [G*NTRK*128];
__device__ float g_f1 [G*NTRK*128];

__device__ __forceinline__ float eluf(float x) { return x > 0.f ? x : expm1f(x); }

// ---- packed f32x2 helpers ----
__device__ __forceinline__ u64 splat2(float a) {
    u64 r; asm("mov.b64 %0, {%1, %1};" : "=l"(r) : "f"(a)); return r;
}
__device__ __forceinline__ void ffma2(u64& c, u64 a, u64 b) {
    asm("fma.rn.f32x2 %0, %1, %2, %0;" : "+l"(c) : "l"(a), "l"(b));
}
__device__ __forceinline__ float2 unpack2(u64 v) {
    float2 f; asm("mov.b64 {%0, %1}, %2;" : "=f"(f.x), "=f"(f.y) : "l"(v)); return f;
}

// ---- 32-k weight chunk staging, 256 threads ----
// MODE 0: W[k][c]; MODE 1: W[k][c]-W[128+k][c]; MODE 2: W[128+k][c]
template<int MODE>
__device__ __forceinline__ void stage_chunk(float* dst, const float* __restrict__ W,
                                            int kc, int tid)
{
    #pragma unroll
    for (int e = 0; e < 4; e++) {
        int i4 = tid + e * 256;               // 0..1023 float4s = 32x128 chunk
        float4 w;
        if (MODE == 0) {
            w = ((const float4*)W)[kc * 1024 + i4];
        } else if (MODE == 1) {
            w = ((const float4*)W)[kc * 1024 + i4];
            float4 w2 = ((const float4*)W)[4096 + kc * 1024 + i4];
            w.x -= w2.x; w.y -= w2.y; w.z -= w2.z; w.w -= w2.w;
        } else {
            w = ((const float4*)W)[4096 + kc * 1024 + i4];
        }
        ((float4*)dst)[i4] = w;
    }
}
// full 128x128 bottom-half stage (for gemm_v2), 256 threads
__device__ __forceinline__ void stage_bot_full(float* Ws, const float* __restrict__ W, int tid) {
    #pragma unroll
    for (int e = 0; e < 16; e++)
        ((float4*)Ws)[tid + e * 256] = ((const float4*)W)[tid + e * 256 + 4096];
}

// ---- GEMM core over one 32-k chunk, 256 threads, 8x8 microtile ----
// Hs: [k][r] ld 132; Ws: [k][c] ld 128.
// tx = tid&15 -> col pairs 2tx+32j (j=0..3); ty = tid>>4 -> rows ty*8..ty*8+7.
// A loads broadcast within half-warps; B u64 loads conflict-free.
__device__ __forceinline__ void zero_acc8(u64 acc[8][4]) {
    #pragma unroll
    for (int i = 0; i < 8; i++)
        #pragma unroll
        for (int j = 0; j < 4; j++) acc[i][j] = 0ull;
}
__device__ __forceinline__ void gemm_chunk(const float* __restrict__ Hs,
                                           const float* __restrict__ Ws,
                                           u64 acc[8][4], int tx, int ty)
{
    #pragma unroll 4
    for (int kk = 0; kk < 32; kk++) {
        const float* arow = &Hs[kk * 132 + ty * 8];
        float4 a0 = *(const float4*)arow;
        float4 a1 = *(const float4*)(arow + 4);
        const u64* br = (const u64*)&Ws[kk * 128];
        u64 b0 = br[tx], b1 = br[tx + 16], b2 = br[tx + 32], b3 = br[tx + 48];
        u64 s;
        s = splat2(a0.x); ffma2(acc[0][0],s,b0); ffma2(acc[0][1],s,b1); ffma2(acc[0][2],s,b2); ffma2(acc[0][3],s,b3);
        s = splat2(a0.y); ffma2(acc[1][0],s,b0); ffma2(acc[1][1],s,b1); ffma2(acc[1][2],s,b2); ffma2(acc[1][3],s,b3);
        s = splat2(a0.z); ffma2(acc[2][0],s,b0); ffma2(acc[2][1],s,b1); ffma2(acc[2][2],s,b2); ffma2(acc[2][3],s,b3);
        s = splat2(a0.w); ffma2(acc[3][0],s,b0); ffma2(acc[3][1],s,b1); ffma2(acc[3][2],s,b2); ffma2(acc[3][3],s,b3);
        s = splat2(a1.x); ffma2(acc[4][0],s,b0); ffma2(acc[4][1],s,b1); ffma2(acc[4][2],s,b2); ffma2(acc[4][3],s,b3);
        s = splat2(a1.y); ffma2(acc[5][0],s,b0); ffma2(acc[5][1],s,b1); ffma2(acc[5][2],s,b2); ffma2(acc[5][3],s,b3);
        s = splat2(a1.z); ffma2(acc[6][0],s,b0); ffma2(acc[6][1],s,b1); ffma2(acc[6][2],s,b2); ffma2(acc[6][3],s,b3);
        s = splat2(a1.w); ffma2(acc[7][0],s,b0); ffma2(acc[7][1],s,b1); ffma2(acc[7][2],s,b2); ffma2(acc[7][3],s,b3);
    }
}
// full 128-k pass with double-buffered weight streaming
template<int MODE>
__device__ __forceinline__ void gemm_pass(const float* __restrict__ Hs, float* Wb,
                                          const float* __restrict__ W,
                                          u64 acc[8][4], int tid, int tx, int ty)
{
    stage_chunk<MODE>(Wb, W, 0, tid);
    __syncthreads();
    #pragma unroll
    for (int kc = 0; kc < 4; kc++) {
        if (kc < 3) stage_chunk<MODE>(Wb + ((kc + 1) & 1) * 4096, W, kc + 1, tid);
        gemm_chunk(Hs + kc * 32 * 132, Wb + (kc & 1) * 4096, acc, tx, ty);
        __syncthreads();
    }
}
__device__ __forceinline__ void store256(const u64 acc[8][4], float* __restrict__ C,
                                         size_t row0, int tx, int ty,
                                         const float* __restrict__ bias)
{
    float2 bv[4] = {{0,0},{0,0},{0,0},{0,0}};
    if (bias) {
        #pragma unroll
        for (int j = 0; j < 4; j++) bv[j] = *(const float2*)&bias[tx * 2 + j * 32];
    }
    #pragma unroll
    for (int ii = 0; ii < 8; ii++) {
        size_t r = row0 + ty * 8 + ii;
        #pragma unroll
        for (int j = 0; j < 4; j++) {
            float2 p = unpack2(acc[ii][j]);
            p.x += bv[j].x; p.y += bv[j].y;
            *(float2*)&C[r * 128 + tx * 2 + j * 32] = p;
        }
    }
}

// =====================================================================
// Node kernels: layer1 -> Hs; pass1 = relu(Hs@W2+b2) -> Yf + Hs;
// then NPASS-1 more weight-streamed GEMM passes.
// 256 threads, 128-row tile, 8x8 microtile, 2 blocks/SM target.
// =====================================================================
template<int IN, int NPASS>
__global__ __launch_bounds__(256, 2)
void node_kernel(const float* __restrict__ X,
                 const float* __restrict__ W1, const float* __restrict__ b1,
                 const float* __restrict__ W2, const float* __restrict__ b2,
                 const float* __restrict__ Wc1, const float* __restrict__ bc1,
                 const float* __restrict__ Wc2, const float* __restrict__ bc2,
                 float* __restrict__ Yf, float* __restrict__ Y1, float* __restrict__ Y2)
{
    extern __shared__ float sm[];
    float* Hs  = sm;                    // 128*132 = 16896
    float* Wb  = Hs + 16896;            // 2*4096
    float* Xin = Wb + 8192;             // 128*IN
    float* W1s = Xin + 128 * IN;        // IN*128
    float* b1s = W1s + IN * 128;        // 128
    const int tid = threadIdx.x;
    const int tx = tid & 15, ty = tid >> 4;
    const size_t row0 = (size_t)blockIdx.x * 128;

    for (int t = tid; t < 128 * IN; t += 256) Xin[t] = X[row0 * IN + t];
    for (int t = tid; t < IN * 128; t += 256) W1s[t] = W1[t];
    if (tid < 128) b1s[tid] = b1[tid];
    __syncthreads();

    // layer 1 -> Hs transposed [c][r]: thread = (row, col-half)
    {
        int r = tid >> 1, ch = (tid & 1) * 64;
        float xr[IN];
        #pragma unroll
        for (int d = 0; d < IN; d++) xr[d] = Xin[r * IN + d];
        #pragma unroll 4
        for (int cc = 0; cc < 64; cc++) {
            int c = ch + cc;
            float a = b1s[c];
            #pragma unroll
            for (int d = 0; d < IN; d++) a = fmaf(xr[d], W1s[d * 128 + c], a);
            Hs[c * 132 + r] = eluf(a);
        }
    }
    // (gemm_pass's initial stage+sync orders Hs writes before reads)

    u64 acc[8][4];
    zero_acc8(acc);
    gemm_pass<0>(Hs, Wb, W2, acc, tid, tx, ty);

    // feats = relu(acc + b2) -> Yf and Hs (transposed, in place)
    {
        float2 bv[4];
        #pragma unroll
        for (int j = 0; j < 4; j++) bv[j] = *(const float2*)&b2[tx * 2 + j * 32];
        #pragma unroll
        for (int ii = 0; ii < 8; ii++) {
            int rr = ty * 8 + ii;
            #pragma unroll
            for (int j = 0; j < 4; j++) {
                float2 p = unpack2(acc[ii][j]);
                float va = fmaxf(p.x + bv[j].x, 0.f);
                float vb = fmaxf(p.y + bv[j].y, 0.f);
                int c = tx * 2 + j * 32;
                float2 o = {va, vb};
                *(float2*)&Yf[(row0 + rr) * 128 + c] = o;
                Hs[c * 132 + rr]       = va;
                Hs[(c + 1) * 132 + rr] = vb;
            }
        }
    }

    zero_acc8(acc);
    if (NPASS == 3) gemm_pass<1>(Hs, Wb, Wc1, acc, tid, tx, ty);
    else            gemm_pass<2>(Hs, Wb, Wc1, acc, tid, tx, ty);
    store256(acc, Y1, row0, tx, ty, (NPASS == 3) ? bc1 : nullptr);

    if (NPASS == 3) {
        zero_acc8(acc);
        gemm_pass<1>(Hs, Wb, Wc2, acc, tid, tx, ty);
        store256(acc, Y2, row0, tx, ty, bc2);
    }
}

// =====================================================================
// V2 = f1 @ Wc2_bot. Monolithic W tile + chunked X staging.
// 256 threads, 8x8 microtile.
// =====================================================================
__global__ __launch_bounds__(256, 2)
void gemm_v2(const float* __restrict__ X, const float* __restrict__ W,
             float* __restrict__ C)
{
    extern __shared__ float sm[];
    float* Ws = sm;              // 16384
    float* Xs = sm + 16384;      // 32*132 transposed [k][row]
    const int tid = threadIdx.x;
    const int tx = tid & 15, ty = tid >> 4;
    const size_t row0 = (size_t)blockIdx.x * 128;

    stage_bot_full(Ws, W, tid);

    u64 acc[8][4];
    zero_acc8(acc);

    for (int kc = 0; kc < 4; kc++) {
        __syncthreads();
        #pragma unroll
        for (int e = 0; e < 4; e++) {
            int t = tid + e * 256;          // 0..1023
            int row = t >> 3;
            int kq  = (t & 7) * 4;
            float4 v = *(const float4*)&X[(row0 + row) * 128 + kc * 32 + kq];
            Xs[(kq + 0) * 132 + row] = v.x;
            Xs[(kq + 1) * 132 + row] = v.y;
            Xs[(kq + 2) * 132 + row] = v.z;
            Xs[(kq + 3) * 132 + row] = v.w;
        }
        __syncthreads();
        gemm_chunk(Xs, Ws + kc * 32 * 128, acc, tx, ty);
    }
    store256(acc, C, row0, tx, ty, nullptr);
}

// =====================================================================
// conv1: kNN(trk -> 16 SVs) + gather-max + ELU -> f1. 512 threads/graph.
// =====================================================================
__global__ __launch_bounds__(512)
void conv1_kernel(const float* __restrict__ trkF, const float* __restrict__ svF,
                  const float* __restrict__ U,    const float* __restrict__ V,
                  float* __restrict__ f1out)
{
    extern __shared__ float sm[];
    float* dsh = sm;                    // 64*130
    float* ssh = dsh + 64 * 130;        // 16*130
    float* vsh = ssh + 16 * 130;        // 16*130
    float* sc  = vsh + 16 * 130;        // 64*17
    float* sn2 = sc + 64 * 17;          // 16
    int*  idxs = (int*)(sn2 + 16);      // 64*8

    const int g   = blockIdx.x;
    const int tid = threadIdx.x;
    const int wid = tid >> 5, lane = tid & 31;
    const float* dg = trkF + (size_t)g * 64 * 128;
    const float* sg = svF  + (size_t)g * 16 * 128;
    const float* Vg = V    + (size_t)g * 16 * 128;
    const float* Ug = U    + (size_t)g * 64 * 128;

    for (int t = tid; t < 64 * 128; t += 512)
        dsh[(t >> 7) * 130 + (t & 127)] = dg[t];
    for (int t = tid; t < 16 * 128; t += 512) {
        int r = t >> 7, c = t & 127;
        ssh[r * 130 + c] = sg[t];
        vsh[r * 130 + c] = Vg[t];
    }
    __syncthreads();

    if (wid < 16) {
        const float* row = &ssh[wid * 130];
        float e0 = row[lane], e1 = row[32 + lane], e2 = row[64 + lane], e3 = row[96 + lane];
        float s = e0*e0 + e1*e1 + e2*e2 + e3*e3;
        #pragma unroll
        for (int off = 16; off > 0; off >>= 1) s += __shfl_xor_sync(~0u, s, off);
        if (lane == 0) sn2[wid] = s;
    }
    __syncthreads();

    {
        int i = tid >> 3, jj = tid & 7;
        u64 a0 = 0ull, a1 = 0ull;
        #pragma unroll 8
        for (int kk = 0; kk < 64; kk++) {
            u64 av = *(const u64*)&dsh[i * 130 + kk * 2];
            u64 b0 = *(const u64*)&ssh[jj * 130 + kk * 2];
            u64 b1 = *(const u64*)&ssh[(jj + 8) * 130 + kk * 2];
            ffma2(a0, av, b0);
            ffma2(a1, av, b1);
        }
        float2 p = unpack2(a0);
        sc[i * 17 + jj]     = sn2[jj]     - 2.f * (p.x + p.y);
        p = unpack2(a1);
        sc[i * 17 + jj + 8] = sn2[jj + 8] - 2.f * (p.x + p.y);
    }
    __syncthreads();

    #pragma unroll
    for (int q = 0; q < 4; q++) {
        int row = wid * 4 + q;
        float mv = (lane < 16) ? sc[row * 17 + lane] : FLT_MAX;
        #pragma unroll
        for (int n = 0; n < KNN; n++) {
            float cv = mv; int ci = lane;
            #pragma unroll
            for (int off = 16; off > 0; off >>= 1) {
                float ov = __shfl_xor_sync(~0u, cv, off);
                int   oi = __shfl_xor_sync(~0u, ci, off);
                if (ov < cv || (ov == cv && oi < ci)) { cv = ov; ci = oi; }
            }
            if (lane == 0) idxs[row * 8 + n] = ci;
            if (lane == ci) mv = FLT_MAX;
        }
    }
    __syncthreads();

    {
        int c = tid & 127, ih = tid >> 7;
        for (int i0 = 0; i0 < 64; i0 += 4) {
            int i = i0 + ih;
            const int* ip = &idxs[i * 8];
            float vmax = -FLT_MAX;
            #pragma unroll
            for (int n = 0; n < KNN; n++) vmax = fmaxf(vmax, vsh[ip[n] * 130 + c]);
            f1out[((size_t)g * 64 + i) * 128 + c] = eluf(Ug[i * 128 + c] + vmax);
        }
    }
}

// =====================================================================
// conv2 + mean pool + head. 512 threads/graph. V loaded into the dead
// dst buffer BEFORE top-k so the LDGs overlap the shuffle phase.
// =====================================================================
__global__ __launch_bounds__(512)
void conv2_head_kernel(const float* __restrict__ trkF, const float* __restrict__ f1,
                       const float* __restrict__ U,    const float* __restrict__ V,
                       const float* __restrict__ Wo1, const float* __restrict__ bo1,
                       const float* __restrict__ Wo2, const float* __restrict__ bo2,
                       const float* __restrict__ Wo3, const float* __restrict__ bo3,
                       const float* __restrict__ Wo4, const float* __restrict__ bo4,
                       float* __restrict__ out, int out_size)
{
    extern __shared__ float sm[];
    float* dsh = sm;                    // 64*130 (trk, later V)
    float* ssh = dsh + 64 * 130;        // 64*130 (f1)
    float* sc  = ssh + 64 * 130;        // 64*65
    float* sn2 = sc + 64 * 65;          // 64
    float* colsum = sn2 + 64;           // 512
    float* pooled = colsum + 512;       // 128
    float* h1 = pooled + 128;           // 64
    float* h2 = h1 + 64;                // 32
    float* h3 = h2 + 32;                // 4
    int*  idxs = (int*)(h3 + 4);        // 64*8

    const int g   = blockIdx.x;
    const int tid = threadIdx.x;
    const int wid = tid >> 5, lane = tid & 31;
    const float* dg = trkF + (size_t)g * 64 * 128;
    const float* sg = f1   + (size_t)g * 64 * 128;
    const float* Vg = V    + (size_t)g * 64 * 128;
    const float* Ug = U    + (size_t)g * 64 * 128;

    for (int t = tid; t < 64 * 128; t += 512) {
        int r = t >> 7, c = t & 127;
        dsh[r * 130 + c] = dg[t];
        ssh[r * 130 + c] = sg[t];
    }
    __syncthreads();

    #pragma unroll
    for (int q = 0; q < 4; q++) {
        int row = wid * 4 + q;
        const float* rp = &ssh[row * 130];
        float e0 = rp[lane], e1 = rp[32 + lane], e2 = rp[64 + lane], e3 = rp[96 + lane];
        float s = e0*e0 + e1*e1 + e2*e2 + e3*e3;
        #pragma unroll
        for (int off = 16; off > 0; off >>= 1) s += __shfl_xor_sync(~0u, s, off);
        if (lane == 0) sn2[row] = s;
    }
    __syncthreads();

    {
        const int tx = tid & 15, ty = tid >> 4;
        u64 acc[2][4];
        #pragma unroll
        for (int a = 0; a < 2; a++)
            #pragma unroll
            for (int b = 0; b < 4; b++) acc[a][b] = 0ull;
        #pragma unroll 8
        for (int kk = 0; kk < 64; kk++) {
            u64 av0 = *(const u64*)&dsh[(ty * 2) * 130 + kk * 2];
            u64 av1 = *(const u64*)&dsh[(ty * 2 + 1) * 130 + kk * 2];
            #pragma unroll
            for (int jj = 0; jj < 4; jj++) {
                u64 bv = *(const u64*)&ssh[(tx + jj * 16) * 130 + kk * 2];
                ffma2(acc[0][jj], av0, bv);
                ffma2(acc[1][jj], av1, bv);
            }
        }
        #pragma unroll
        for (int ii = 0; ii < 2; ii++)
            #pragma unroll
            for (int jj = 0; jj < 4; jj++) {
                float2 p = unpack2(acc[ii][jj]);
                int j = tx + jj * 16;
                sc[(ty * 2 + ii) * 65 + j] = sn2[j] - 2.f * (p.x + p.y);
            }
    }
    __syncthreads();

    // overwrite dsh with V tile (LDGs overlap the top-k shuffles below)
    for (int t = tid; t < 64 * 128; t += 512)
        dsh[(t >> 7) * 130 + (t & 127)] = Vg[t];

    // warp-parallel top-8 over 64 candidates (2 per lane)
    #pragma unroll
    for (int q = 0; q < 4; q++) {
        int row = wid * 4 + q;
        float v0 = sc[row * 65 + lane];
        float v1 = sc[row * 65 + 32 + lane];
        #pragma unroll
        for (int n = 0; n < KNN; n++) {
            float cv; int ci;
            if (v1 < v0) { cv = v1; ci = lane + 32; }
            else         { cv = v0; ci = lane; }
            #pragma unroll
            for (int off = 16; off > 0; off >>= 1) {
                float ov = __shfl_xor_sync(~0u, cv, off);
                int   oi = __shfl_xor_sync(~0u, ci, off);
                if (ov < cv || (ov == cv && oi < ci)) { cv = ov; ci = oi; }
            }
            if (lane == 0) idxs[row * 8 + n] = ci;
            if (ci == lane)           v0 = FLT_MAX;
            else if (ci == lane + 32) v1 = FLT_MAX;
        }
    }
    __syncthreads();

    {
        int c = tid & 127, ih = tid >> 7;
        float csum = 0.f;
        for (int i0 = 0; i0 < 64; i0 += 4) {
            int i = i0 + ih;
            const int* ip = &idxs[i * 8];
            float vmax = -FLT_MAX;
            #pragma unroll
            for (int n = 0; n < KNN; n++) vmax = fmaxf(vmax, dsh[ip[n] * 130 + c]);
            csum += eluf(Ug[i * 128 + c] + vmax);
        }
        colsum[ih * 128 + c] = csum;
    }
    __syncthreads();
    if (tid < 128)
        pooled[tid] = (colsum[tid] + colsum[128 + tid] + colsum[256 + tid] + colsum[384 + tid]) * (1.f / 64.f);
    __syncthreads();
    if (tid < 64) {
        float a = bo1[tid];
        #pragma unroll 8
        for (int d = 0; d < 128; d++) a += pooled[d] * Wo1[d * 64 + tid];
        h1[tid] = eluf(a);
    }
    __syncthreads();
    if (tid < 32) {
        float a = bo2[tid];
        #pragma unroll 8
        for (int d = 0; d < 64; d++) a += h1[d] * Wo2[d * 32 + tid];
        h2[tid] = eluf(a);
    }
    __syncthreads();
    if (tid < 4) {
        float a = bo3[tid];
        #pragma unroll
        for (int d = 0; d < 32; d++) a += h2[d] * Wo3[d * 4 + tid];
        h3[tid] = eluf(a);
    }
    __syncthreads();
    if (tid == 0) {
        float a = bo4[0];
        #pragma unroll
        for (int d = 0; d < 4; d++) a += h3[d] * Wo4[d];
        out[g] = a;
        if (out_size >= 2 * G) out[G + g] = (float)g;
    }
}

// ---------------- launch ----------------
extern "C" void kernel_launch(void* const* d_in, const int* in_sizes, int n_in,
                              void* d_out, int out_size)
{
    const float* x_sv   = (const float*)d_in[0];
    const float* x_trk  = (const float*)d_in[1];
    const float* W_sv1  = (const float*)d_in[2];
    const float* b_sv1  = (const float*)d_in[3];
    const float* W_sv2  = (const float*)d_in[4];
    const float* b_sv2  = (const float*)d_in[5];
    const float* W_trk1 = (const float*)d_in[6];
    const float* b_trk1 = (const float*)d_in[7];
    const float* W_trk2 = (const float*)d_in[8];
    const float* b_trk2 = (const float*)d_in[9];
    const float* W_c1   = (const float*)d_in[10];
    const float* b_c1   = (const float*)d_in[11];
    const float* W_c2   = (const float*)d_in[12];
    const float* b_c2   = (const float*)d_in[13];
    const float* W_o1   = (const float*)d_in[14];
    const float* b_o1   = (const float*)d_in[15];
    const float* W_o2   = (const float*)d_in[16];
    const float* b_o2   = (const float*)d_in[17];
    const float* W_o3   = (const float*)d_in[18];
    const float* b_o3   = (const float*)d_in[19];
    const float* W_o4   = (const float*)d_in[20];
    const float* b_o4   = (const float*)d_in[21];
    float* out = (float*)d_out;

    float *p_sv, *p_trk, *p_U1, *p_U2, *p_V1, *p_V2, *p_f1;
    cudaGetSymbolAddress((void**)&p_sv,  g_sv);
    cudaGetSymbolAddress((void**)&p_trk, g_trk);
    cudaGetSymbolAddress((void**)&p_U1,  g_U1);
    cudaGetSymbolAddress((void**)&p_U2,  g_U2);
    cudaGetSymbolAddress((void**)&p_V1,  g_V1);
    cudaGetSymbolAddress((void**)&p_V2,  g_V2);
    cudaGetSymbolAddress((void**)&p_f1,  g_f1);

    const int smem_a = (16896 + 8192 + 128*2 + 2*128 + 128) * 4;
    const int smem_b = (16896 + 8192 + 128*8 + 8*128 + 128) * 4;
    const int smem_g = (16384 + 32*132) * 4;
    const int smem_c = (64*130 + 16*130 + 16*130 + 64*17 + 16) * 4 + 64*8*4;
    const int smem_d = (64*130 + 64*130 + 64*65 + 64 + 512 + 128 + 64 + 32 + 4) * 4 + 64*8*4;

    (void)cudaFuncSetAttribute(node_kernel<2,2>,  cudaFuncAttributeMaxDynamicSharedMemorySize, smem_a);
    (void)cudaFuncSetAttribute(node_kernel<8,3>,  cudaFuncAttributeMaxDynamicSharedMemorySize, smem_b);
    (void)cudaFuncSetAttribute(gemm_v2,           cudaFuncAttributeMaxDynamicSharedMemorySize, smem_g);
    (void)cudaFuncSetAttribute(conv1_kernel,      cudaFuncAttributeMaxDynamicSharedMemorySize, smem_c);
    (void)cudaFuncSetAttribute(conv2_head_kernel, cudaFuncAttributeMaxDynamicSharedMemorySize, smem_d);

    // A: sv MLP + V1
    node_kernel<2,2><<<G * NSV / 128, 256, smem_a>>>(
        x_sv, W_sv1, b_sv1, W_sv2, b_sv2, W_c1, nullptr, nullptr, nullptr,
        p_sv, p_V1, nullptr);

    // B: trk MLP + U1 + U2
    node_kernel<8,3><<<G * NTRK / 128, 256, smem_b>>>(
        x_trk, W_trk1, b_trk1, W_trk2, b_trk2, W_c1, b_c1, W_c2, b_c2,
        p_trk, p_U1, p_U2);

    // C: conv1 -> f1
    conv1_kernel<<<G, 512, smem_c>>>(p_trk, p_sv, p_U1, p_V1, p_f1);

    // V2 = f1 @ Wc2_bot
    gemm_v2<<<G * NTRK / 128, 256, smem_g>>>(p_f1, W_c2, p_V2);

    // D: conv2 + head
    conv2_head_kernel<<<G, 512, smem_d>>>(p_trk, p_f1, p_U2, p_V2,
        W_o1, b_o1, W_o2, b_o2, W_o3, b_o3, W_o4, b_o4, out, out_size);
}